// round 1
// baseline (speedup 1.0000x reference)
#include <cuda_runtime.h>
#include <cuda_bf16.h>
#include <cstdint>

// ============================================================================
// OctreeAttention: QKV proj (tf32 mma GEMM) -> per-window attention (warp/head)
//                  -> output proj (tf32 mma GEMM)
// N_WIN=8192, K=32, H=12, C=192, d=16
// ============================================================================

#define N_WIN 8192
#define KWIN  32
#define HEADS 12
#define CDIM  192
#define DHEAD 16
#define SCALE 0.25f
// qkv scratch: [N_WIN*KWIN, 576], attn scratch: [N_WIN*KWIN, 192]
__device__ float g_qkv[262144 * 576];
__device__ float g_att[262144 * 192];

// ----------------------------------------------------------------------------
// tf32 helpers
// ----------------------------------------------------------------------------
__device__ __forceinline__ uint32_t f2tf(float f) {
    uint32_t r;
    asm("cvt.rna.tf32.f32 %0, %1;" : "=r"(r) : "f"(f));
    return r;
}

#define MMA_TF32(d, a, b)                                                     \
    asm volatile(                                                             \
        "mma.sync.aligned.m16n8k8.row.col.f32.tf32.tf32.f32 "                 \
        "{%0,%1,%2,%3}, {%4,%5,%6,%7}, {%8,%9}, {%0,%1,%2,%3};\n"             \
        : "+f"(d[0]), "+f"(d[1]), "+f"(d[2]), "+f"(d[3])                      \
        : "r"(a[0]), "r"(a[1]), "r"(a[2]), "r"(a[3]), "r"(b[0]), "r"(b[1]))

// ----------------------------------------------------------------------------
// GEMM: C[M,N] = A[M,Kd] * B[N,Kd]^T + bias[N]
// BM=128, BN=64, BK=32, 256 threads, double-buffered smem, tf32 mma.
// Requires M%128==0, N%64==0, Kd%32==0 (holds: M=262144, N in {576,192}, Kd=192)
// ----------------------------------------------------------------------------
#define BM 128
#define BN 64
#define BK 32
#define ASTR 36  // BK + 4 pad: conflict-free fragment loads
#define A_BUF (BM * ASTR)
#define B_BUF (BN * ASTR)

__global__ void __launch_bounds__(256) gemm_tf32(
    const float* __restrict__ A, const float* __restrict__ B,
    const float* __restrict__ bias, float* __restrict__ C,
    int M, int N, int Kd)
{
    extern __shared__ uint32_t sm_g[];
    uint32_t* As = sm_g;                // [2][BM*ASTR]
    uint32_t* Bs = sm_g + 2 * A_BUF;    // [2][BN*ASTR]

    const int tid = threadIdx.x;
    const int m0 = blockIdx.x * BM;
    const int n0 = blockIdx.y * BN;
    const int ar = tid >> 3;           // 0..31
    const int ac = (tid & 7) * 4;      // 0..28
    const int KC = Kd >> 5;            // k-chunks of 32

    const int lane = tid & 31, warp = tid >> 5;
    const int wm = warp & 3, wn = warp >> 2;
    const int g = lane >> 2, t = lane & 3;

    float4 aR[4];
    float4 bR[2];

    // prologue: load chunk 0 and store to buffer 0
#pragma unroll
    for (int i = 0; i < 4; i++)
        aR[i] = *(const float4*)(A + (size_t)(m0 + ar + 32 * i) * Kd + ac);
#pragma unroll
    for (int i = 0; i < 2; i++)
        bR[i] = *(const float4*)(B + (size_t)(n0 + ar + 32 * i) * Kd + ac);
#pragma unroll
    for (int i = 0; i < 4; i++) {
        uint4 u = make_uint4(f2tf(aR[i].x), f2tf(aR[i].y), f2tf(aR[i].z), f2tf(aR[i].w));
        *(uint4*)(As + (ar + 32 * i) * ASTR + ac) = u;
    }
#pragma unroll
    for (int i = 0; i < 2; i++) {
        uint4 u = make_uint4(f2tf(bR[i].x), f2tf(bR[i].y), f2tf(bR[i].z), f2tf(bR[i].w));
        *(uint4*)(Bs + (ar + 32 * i) * ASTR + ac) = u;
    }
    __syncthreads();

    float acc[2][4][4];
#pragma unroll
    for (int mt = 0; mt < 2; mt++)
#pragma unroll
        for (int nt = 0; nt < 4; nt++)
#pragma unroll
            for (int i = 0; i < 4; i++) acc[mt][nt][i] = 0.0f;

    for (int kc = 0; kc < KC; kc++) {
        if (kc + 1 < KC) {
            const int kofs = (kc + 1) * BK + ac;
#pragma unroll
            for (int i = 0; i < 4; i++)
                aR[i] = *(const float4*)(A + (size_t)(m0 + ar + 32 * i) * Kd + kofs);
#pragma unroll
            for (int i = 0; i < 2; i++)
                bR[i] = *(const float4*)(B + (size_t)(n0 + ar + 32 * i) * Kd + kofs);
        }

        const uint32_t* as = As + (kc & 1) * A_BUF;
        const uint32_t* bs = Bs + (kc & 1) * B_BUF;
#pragma unroll
        for (int ks = 0; ks < 4; ks++) {
            const int k0 = ks * 8;
            uint32_t af[2][4];
#pragma unroll
            for (int mt = 0; mt < 2; mt++) {
                const int r = wm * 32 + mt * 16 + g;
                af[mt][0] = as[r * ASTR + k0 + t];
                af[mt][1] = as[(r + 8) * ASTR + k0 + t];
                af[mt][2] = as[r * ASTR + k0 + t + 4];
                af[mt][3] = as[(r + 8) * ASTR + k0 + t + 4];
            }
            uint32_t bf[4][2];
#pragma unroll
            for (int nt = 0; nt < 4; nt++) {
                const int nn = wn * 32 + nt * 8 + g;
                bf[nt][0] = bs[nn * ASTR + k0 + t];
                bf[nt][1] = bs[nn * ASTR + k0 + t + 4];
            }
#pragma unroll
            for (int mt = 0; mt < 2; mt++)
#pragma unroll
                for (int nt = 0; nt < 4; nt++)
                    MMA_TF32(acc[mt][nt], af[mt], bf[nt]);
        }

        if (kc + 1 < KC) {
            const int nb = (kc + 1) & 1;
#pragma unroll
            for (int i = 0; i < 4; i++) {
                uint4 u = make_uint4(f2tf(aR[i].x), f2tf(aR[i].y), f2tf(aR[i].z), f2tf(aR[i].w));
                *(uint4*)(As + nb * A_BUF + (ar + 32 * i) * ASTR + ac) = u;
            }
#pragma unroll
            for (int i = 0; i < 2; i++) {
                uint4 u = make_uint4(f2tf(bR[i].x), f2tf(bR[i].y), f2tf(bR[i].z), f2tf(bR[i].w));
                *(uint4*)(Bs + nb * B_BUF + (ar + 32 * i) * ASTR + ac) = u;
            }
            __syncthreads();
        }
    }

    // epilogue: add bias, store float2 pairs
#pragma unroll
    for (int mt = 0; mt < 2; mt++) {
#pragma unroll
        for (int nt = 0; nt < 4; nt++) {
            const int row = m0 + wm * 32 + mt * 16 + g;
            const int col = n0 + wn * 32 + nt * 8 + 2 * t;
            const float b0 = bias[col], b1 = bias[col + 1];
            float2 v0 = make_float2(acc[mt][nt][0] + b0, acc[mt][nt][1] + b1);
            float2 v1 = make_float2(acc[mt][nt][2] + b0, acc[mt][nt][3] + b1);
            *(float2*)(C + (size_t)row * N + col) = v0;
            *(float2*)(C + (size_t)(row + 8) * N + col) = v1;
        }
    }
}

// ----------------------------------------------------------------------------
// Attention: 1 CTA per window, 384 threads, warp h == head h, lane == query row.
// qkv layout per row (len 576): [q(0..191) | k(192..383) | v(384..575)],
// within each: col = h*16 + d.
// ----------------------------------------------------------------------------
#define QS 584                      // 576 + 8 pad (float4-aligned)
#define SM_QKV (32 * QS)            // 18688 floats
#define SM_RP  1056                 // 32*33 ints
#define SM_MK  1056                 // 32*33 floats
#define SM_TBL 1836                 // 153*12 floats
#define ATTN_SMEM ((SM_QKV + SM_RP + SM_MK + SM_TBL) * 4)

__global__ void __launch_bounds__(384, 2) attn_kernel(
    const float* __restrict__ qkv, const int* __restrict__ rel_pos,
    const float* __restrict__ mask, const float* __restrict__ table,
    float* __restrict__ out)
{
    extern __shared__ float sm[];
    float* s_qkv   = sm;
    int*   s_rp    = (int*)(sm + SM_QKV);
    float* s_mask  = sm + SM_QKV + SM_RP;
    float* s_table = sm + SM_QKV + SM_RP + SM_MK;

    const int n = blockIdx.x;
    const int tid = threadIdx.x;

    // stage qkv window: 32 rows x 144 float4
    {
        const float4* gq = (const float4*)(qkv + (size_t)n * 32 * 576);
        for (int i = tid; i < 32 * 144; i += 384) {
            const int r = i / 144, c = i - r * 144;
            ((float4*)(s_qkv + r * QS))[c] = gq[r * 144 + c];
        }
    }
    // stage rpe table
    for (int i = tid; i < SM_TBL; i += 384) s_table[i] = table[i];
    // stage rel_pos (packed, pre-offset) + mask
    {
        const int* rp = rel_pos + (size_t)n * 3072;
        const float* mk = mask + (size_t)n * 1024;
        for (int p = tid; p < 1024; p += 384) {
            int e0 = min(25, max(-25, rp[3 * p + 0])) + 25;        // axis 0: rows 0..50
            int e1 = min(25, max(-25, rp[3 * p + 1])) + 25 + 51;   // axis 1: rows 51..101
            int e2 = min(25, max(-25, rp[3 * p + 2])) + 25 + 102;  // axis 2: rows 102..152
            const int qq = p >> 5, kk = p & 31;
            s_rp[qq * 33 + kk] = e0 | (e1 << 8) | (e2 << 16);
            s_mask[qq * 33 + kk] = mk[p];
        }
    }
    __syncthreads();

    const int h = tid >> 5;   // head (warp)
    const int qq = tid & 31;  // query row (lane)

    // q row -> registers, pre-scaled
    float qr[16];
    {
        const float4* qp = (const float4*)(s_qkv + qq * QS + h * 16);
#pragma unroll
        for (int j = 0; j < 4; j++) {
            float4 v = qp[j];
            qr[4 * j + 0] = v.x * SCALE;
            qr[4 * j + 1] = v.y * SCALE;
            qr[4 * j + 2] = v.z * SCALE;
            qr[4 * j + 3] = v.w * SCALE;
        }
    }

    // scores: sc[kk] = q . k[kk]   (k rows are warp-uniform broadcasts)
    float sc[32];
#pragma unroll
    for (int kk = 0; kk < 32; kk++) {
        const float4* kp = (const float4*)(s_qkv + kk * QS + 192 + h * 16);
        float a = 0.0f;
#pragma unroll
        for (int j = 0; j < 4; j++) {
            float4 v = kp[j];
            a += qr[4 * j + 0] * v.x + qr[4 * j + 1] * v.y +
                 qr[4 * j + 2] * v.z + qr[4 * j + 3] * v.w;
        }
        sc[kk] = a;
    }

    // RPE bias + mask
#pragma unroll
    for (int kk = 0; kk < 32; kk++) {
        const int pk = s_rp[qq * 33 + kk];
        const float b = s_table[(pk & 255) * 12 + h] +
                        s_table[((pk >> 8) & 255) * 12 + h] +
                        s_table[((pk >> 16) & 255) * 12 + h];
        sc[kk] += b + s_mask[qq * 33 + kk];
    }

    // softmax over kk (all in-lane)
    float m = sc[0];
#pragma unroll
    for (int kk = 1; kk < 32; kk++) m = fmaxf(m, sc[kk]);
    float s = 0.0f;
#pragma unroll
    for (int kk = 0; kk < 32; kk++) {
        sc[kk] = __expf(sc[kk] - m);
        s += sc[kk];
    }
    const float inv = 1.0f / s;

    // out = P @ V (v rows warp-uniform broadcasts), normalize at the end
    float o[16];
#pragma unroll
    for (int j = 0; j < 16; j++) o[j] = 0.0f;
#pragma unroll
    for (int kk = 0; kk < 32; kk++) {
        const float4* vp = (const float4*)(s_qkv + kk * QS + 384 + h * 16);
        const float p = sc[kk];
#pragma unroll
        for (int j = 0; j < 4; j++) {
            float4 v = vp[j];
            o[4 * j + 0] += p * v.x;
            o[4 * j + 1] += p * v.y;
            o[4 * j + 2] += p * v.z;
            o[4 * j + 3] += p * v.w;
        }
    }

    float* op = out + (size_t)(n * 32 + qq) * 192 + h * 16;
#pragma unroll
    for (int j = 0; j < 4; j++) {
        float4 w = make_float4(o[4 * j + 0] * inv, o[4 * j + 1] * inv,
                               o[4 * j + 2] * inv, o[4 * j + 3] * inv);
        ((float4*)op)[j] = w;
    }
}

// ----------------------------------------------------------------------------
// launch
// ----------------------------------------------------------------------------
#define GEMM_SMEM ((2 * A_BUF + 2 * B_BUF) * 4)

extern "C" void kernel_launch(void* const* d_in, const int* in_sizes, int n_in,
                              void* d_out, int out_size)
{
    // identify inputs by element count (all distinct) — robust to ordering
    const float* data = nullptr;
    const int* rel_pos = nullptr;
    const float* mask = nullptr;
    const float* qkv_w = nullptr;
    const float* qkv_b = nullptr;
    const float* proj_w = nullptr;
    const float* proj_b = nullptr;
    const float* rpe_table = nullptr;
    for (int i = 0; i < n_in; i++) {
        switch (in_sizes[i]) {
            case 262144 * 192:      data = (const float*)d_in[i]; break;       // 50331648
            case 8192 * 32 * 32 * 3: rel_pos = (const int*)d_in[i]; break;     // 25165824
            case 8192 * 32 * 32:    mask = (const float*)d_in[i]; break;       // 8388608
            case 576 * 192:         qkv_w = (const float*)d_in[i]; break;      // 110592
            case 576:               qkv_b = (const float*)d_in[i]; break;
            case 192 * 192:         proj_w = (const float*)d_in[i]; break;     // 36864
            case 192:               proj_b = (const float*)d_in[i]; break;
            case 153 * 12:          rpe_table = (const float*)d_in[i]; break;  // 1836
            default: break;
        }
    }
    float* out = (float*)d_out;

    float* qkv_s = nullptr;
    float* att_s = nullptr;
    cudaGetSymbolAddress((void**)&qkv_s, g_qkv);
    cudaGetSymbolAddress((void**)&att_s, g_att);

    cudaFuncSetAttribute(gemm_tf32, cudaFuncAttributeMaxDynamicSharedMemorySize, GEMM_SMEM);
    cudaFuncSetAttribute(attn_kernel, cudaFuncAttributeMaxDynamicSharedMemorySize, ATTN_SMEM);

    // 1. QKV projection: [262144,192] @ [576,192]^T + b -> g_qkv
    gemm_tf32<<<dim3(262144 / BM, 576 / BN), 256, GEMM_SMEM>>>(
        data, qkv_w, qkv_b, qkv_s, 262144, 576, 192);

    // 2. per-window attention -> g_att
    attn_kernel<<<N_WIN, 384, ATTN_SMEM>>>(qkv_s, rel_pos, mask, rpe_table, att_s);

    // 3. output projection: [262144,192] @ [192,192]^T + b -> out
    gemm_tf32<<<dim3(262144 / BM, 192 / BN), 256, GEMM_SMEM>>>(
        att_s, proj_w, proj_b, out, 262144, 192, 192);
}

// round 3
// speedup vs baseline: 1.0083x; 1.0083x over previous
#include <cuda_runtime.h>
#include <cuda_bf16.h>
#include <cstdint>

// ============================================================================
// OctreeAttention: QKV proj (tf32 mma GEMM) -> per-window attention (warp/head)
//                  -> output proj (tf32 mma GEMM)
// N_WIN=8192, K=32, H=12, C=192, d=16
// R3 (= R2 resubmit after infra flake): n-fast grid (A reuse via L2),
// BM=256 warp-tile 64x32 (halved LDS bytes/MAC), vectorized rel_pos/mask staging.
// ============================================================================

#define N_WIN 8192
#define KWIN  32
#define HEADS 12
#define CDIM  192
#define DHEAD 16
#define SCALE 0.25f
// qkv scratch: [N_WIN*KWIN, 576], attn scratch: [N_WIN*KWIN, 192]
__device__ float g_qkv[262144 * 576];
__device__ float g_att[262144 * 192];

// ----------------------------------------------------------------------------
// tf32 helpers
// ----------------------------------------------------------------------------
__device__ __forceinline__ uint32_t f2tf(float f) {
    uint32_t r;
    asm("cvt.rna.tf32.f32 %0, %1;" : "=r"(r) : "f"(f));
    return r;
}

#define MMA_TF32(d, a, b)                                                     \
    asm volatile(                                                             \
        "mma.sync.aligned.m16n8k8.row.col.f32.tf32.tf32.f32 "                 \
        "{%0,%1,%2,%3}, {%4,%5,%6,%7}, {%8,%9}, {%0,%1,%2,%3};\n"             \
        : "+f"(d[0]), "+f"(d[1]), "+f"(d[2]), "+f"(d[3])                      \
        : "r"(a[0]), "r"(a[1]), "r"(a[2]), "r"(a[3]), "r"(b[0]), "r"(b[1]))

// ----------------------------------------------------------------------------
// GEMM: C[M,N] = A[M,Kd] * B[N,Kd]^T + bias[N]
// BM=256, BN=64, BK=32, 256 threads (8 warps, 4x2), warp tile 64x32,
// double-buffered smem, tf32 mma. Grid: (N/BN fast, M/BM slow).
// Requires M%256==0, N%64==0, Kd%32==0 (holds: M=262144, N in {576,192}, Kd=192)
// ----------------------------------------------------------------------------
#define BM 256
#define BN 64
#define BK 32
#define ASTR 36  // BK + 4 pad: conflict-free fragment loads
#define A_BUF (BM * ASTR)
#define B_BUF (BN * ASTR)

__global__ void __launch_bounds__(256) gemm_tf32(
    const float* __restrict__ A, const float* __restrict__ B,
    const float* __restrict__ bias, float* __restrict__ C,
    int M, int N, int Kd)
{
    extern __shared__ uint32_t sm_g[];
    uint32_t* As = sm_g;                // [2][BM*ASTR]
    uint32_t* Bs = sm_g + 2 * A_BUF;    // [2][BN*ASTR]

    const int tid = threadIdx.x;
    const int n0 = blockIdx.x * BN;    // n is the FAST grid dim (A reuse in L2)
    const int m0 = blockIdx.y * BM;
    const int ar = tid >> 3;           // 0..31
    const int ac = (tid & 7) * 4;      // 0..28
    const int KC = Kd >> 5;            // k-chunks of 32

    const int lane = tid & 31, warp = tid >> 5;
    const int wm = warp >> 1, wn = warp & 1;   // 4 x 2 warp grid
    const int g = lane >> 2, t = lane & 3;

    float4 aR[8];
    float4 bR[2];

    // prologue: load chunk 0 and store to buffer 0
#pragma unroll
    for (int i = 0; i < 8; i++)
        aR[i] = *(const float4*)(A + (size_t)(m0 + ar + 32 * i) * Kd + ac);
#pragma unroll
    for (int i = 0; i < 2; i++)
        bR[i] = *(const float4*)(B + (size_t)(n0 + ar + 32 * i) * Kd + ac);
#pragma unroll
    for (int i = 0; i < 8; i++) {
        uint4 u = make_uint4(f2tf(aR[i].x), f2tf(aR[i].y), f2tf(aR[i].z), f2tf(aR[i].w));
        *(uint4*)(As + (ar + 32 * i) * ASTR + ac) = u;
    }
#pragma unroll
    for (int i = 0; i < 2; i++) {
        uint4 u = make_uint4(f2tf(bR[i].x), f2tf(bR[i].y), f2tf(bR[i].z), f2tf(bR[i].w));
        *(uint4*)(Bs + (ar + 32 * i) * ASTR + ac) = u;
    }
    __syncthreads();

    float acc[4][4][4];
#pragma unroll
    for (int mt = 0; mt < 4; mt++)
#pragma unroll
        for (int nt = 0; nt < 4; nt++)
#pragma unroll
            for (int i = 0; i < 4; i++) acc[mt][nt][i] = 0.0f;

    for (int kc = 0; kc < KC; kc++) {
        if (kc + 1 < KC) {
            const int kofs = (kc + 1) * BK + ac;
#pragma unroll
            for (int i = 0; i < 8; i++)
                aR[i] = *(const float4*)(A + (size_t)(m0 + ar + 32 * i) * Kd + kofs);
#pragma unroll
            for (int i = 0; i < 2; i++)
                bR[i] = *(const float4*)(B + (size_t)(n0 + ar + 32 * i) * Kd + kofs);
        }

        const uint32_t* as = As + (kc & 1) * A_BUF;
        const uint32_t* bs = Bs + (kc & 1) * B_BUF;
#pragma unroll
        for (int ks = 0; ks < 4; ks++) {
            const int k0 = ks * 8;
            uint32_t af[4][4];
#pragma unroll
            for (int mt = 0; mt < 4; mt++) {
                const int r = wm * 64 + mt * 16 + g;
                af[mt][0] = as[r * ASTR + k0 + t];
                af[mt][1] = as[(r + 8) * ASTR + k0 + t];
                af[mt][2] = as[r * ASTR + k0 + t + 4];
                af[mt][3] = as[(r + 8) * ASTR + k0 + t + 4];
            }
            uint32_t bf[4][2];
#pragma unroll
            for (int nt = 0; nt < 4; nt++) {
                const int nn = wn * 32 + nt * 8 + g;
                bf[nt][0] = bs[nn * ASTR + k0 + t];
                bf[nt][1] = bs[nn * ASTR + k0 + t + 4];
            }
#pragma unroll
            for (int mt = 0; mt < 4; mt++)
#pragma unroll
                for (int nt = 0; nt < 4; nt++)
                    MMA_TF32(acc[mt][nt], af[mt], bf[nt]);
        }

        if (kc + 1 < KC) {
            const int nb = (kc + 1) & 1;
#pragma unroll
            for (int i = 0; i < 8; i++) {
                uint4 u = make_uint4(f2tf(aR[i].x), f2tf(aR[i].y), f2tf(aR[i].z), f2tf(aR[i].w));
                *(uint4*)(As + nb * A_BUF + (ar + 32 * i) * ASTR + ac) = u;
            }
#pragma unroll
            for (int i = 0; i < 2; i++) {
                uint4 u = make_uint4(f2tf(bR[i].x), f2tf(bR[i].y), f2tf(bR[i].z), f2tf(bR[i].w));
                *(uint4*)(Bs + nb * B_BUF + (ar + 32 * i) * ASTR + ac) = u;
            }
            __syncthreads();
        }
    }

    // epilogue: add bias, store float2 pairs
#pragma unroll
    for (int mt = 0; mt < 4; mt++) {
#pragma unroll
        for (int nt = 0; nt < 4; nt++) {
            const int row = m0 + wm * 64 + mt * 16 + g;
            const int col = n0 + wn * 32 + nt * 8 + 2 * t;
            const float b0 = bias[col], b1 = bias[col + 1];
            float2 v0 = make_float2(acc[mt][nt][0] + b0, acc[mt][nt][1] + b1);
            float2 v1 = make_float2(acc[mt][nt][2] + b0, acc[mt][nt][3] + b1);
            *(float2*)(C + (size_t)row * N + col) = v0;
            *(float2*)(C + (size_t)(row + 8) * N + col) = v1;
        }
    }
}

// ----------------------------------------------------------------------------
// Attention: 1 CTA per window, 384 threads, warp h == head h, lane == query row.
// qkv layout per row (len 576): [q(0..191) | k(192..383) | v(384..575)],
// within each: col = h*16 + d.
// ----------------------------------------------------------------------------
#define QS 584                      // 576 + 8 pad (float4-aligned)
#define SM_QKV (32 * QS)            // 18688 floats
#define SM_RP  1056                 // 32*33 ints
#define SM_MK  1056                 // 32*33 floats
#define SM_TBL 1836                 // 153*12 floats
#define ATTN_SMEM ((SM_QKV + SM_RP + SM_MK + SM_TBL) * 4)

__device__ __forceinline__ int rp_pack(int a, int b, int c) {
    int e0 = min(25, max(-25, a)) + 25;         // axis 0: rows 0..50
    int e1 = min(25, max(-25, b)) + 25 + 51;    // axis 1: rows 51..101
    int e2 = min(25, max(-25, c)) + 25 + 102;   // axis 2: rows 102..152
    return e0 | (e1 << 8) | (e2 << 16);
}

__global__ void __launch_bounds__(384, 2) attn_kernel(
    const float* __restrict__ qkv, const int* __restrict__ rel_pos,
    const float* __restrict__ mask, const float* __restrict__ table,
    float* __restrict__ out)
{
    extern __shared__ float sm[];
    float* s_qkv   = sm;
    int*   s_rp    = (int*)(sm + SM_QKV);
    float* s_mask  = sm + SM_QKV + SM_RP;
    float* s_table = sm + SM_QKV + SM_RP + SM_MK;

    const int n = blockIdx.x;
    const int tid = threadIdx.x;

    // stage qkv window: 32 rows x 144 float4
    {
        const float4* gq = (const float4*)(qkv + (size_t)n * 32 * 576);
        for (int i = tid; i < 32 * 144; i += 384) {
            const int r = i / 144, c = i - r * 144;
            ((float4*)(s_qkv + r * QS))[c] = gq[r * 144 + c];
        }
    }
    // stage rpe table
    for (int i = tid; i < SM_TBL; i += 384) s_table[i] = table[i];
    // stage rel_pos: 256 threads x 4 pairs via 3 int4 loads (12 ints = 4 pairs)
    if (tid < 256) {
        const int4* rp4 = (const int4*)(rel_pos + (size_t)n * 3072) + tid * 3;
        const int4 v0 = rp4[0], v1 = rp4[1], v2 = rp4[2];
        const int p0 = tid * 4;
        const int q0 = p0 >> 5, k0 = p0 & 31;    // 4 consecutive kk, same qq
        int* dst = s_rp + q0 * 33 + k0;
        dst[0] = rp_pack(v0.x, v0.y, v0.z);
        dst[1] = rp_pack(v0.w, v1.x, v1.y);
        dst[2] = rp_pack(v1.z, v1.w, v2.x);
        dst[3] = rp_pack(v2.y, v2.z, v2.w);
        // stage mask: float4 per thread
        const float4 mv = ((const float4*)(mask + (size_t)n * 1024))[tid];
        float* md = s_mask + q0 * 33 + k0;
        md[0] = mv.x; md[1] = mv.y; md[2] = mv.z; md[3] = mv.w;
    }
    __syncthreads();

    const int h = tid >> 5;   // head (warp)
    const int qq = tid & 31;  // query row (lane)

    // q row -> registers, pre-scaled
    float qr[16];
    {
        const float4* qp = (const float4*)(s_qkv + qq * QS + h * 16);
#pragma unroll
        for (int j = 0; j < 4; j++) {
            float4 v = qp[j];
            qr[4 * j + 0] = v.x * SCALE;
            qr[4 * j + 1] = v.y * SCALE;
            qr[4 * j + 2] = v.z * SCALE;
            qr[4 * j + 3] = v.w * SCALE;
        }
    }

    // scores: sc[kk] = q . k[kk]   (k rows are warp-uniform broadcasts)
    float sc[32];
#pragma unroll
    for (int kk = 0; kk < 32; kk++) {
        const float4* kp = (const float4*)(s_qkv + kk * QS + 192 + h * 16);
        float a = 0.0f;
#pragma unroll
        for (int j = 0; j < 4; j++) {
            float4 v = kp[j];
            a += qr[4 * j + 0] * v.x + qr[4 * j + 1] * v.y +
                 qr[4 * j + 2] * v.z + qr[4 * j + 3] * v.w;
        }
        sc[kk] = a;
    }

    // RPE bias + mask
#pragma unroll
    for (int kk = 0; kk < 32; kk++) {
        const int pk = s_rp[qq * 33 + kk];
        const float b = s_table[(pk & 255) * 12 + h] +
                        s_table[((pk >> 8) & 255) * 12 + h] +
                        s_table[((pk >> 16) & 255) * 12 + h];
        sc[kk] += b + s_mask[qq * 33 + kk];
    }

    // softmax over kk (all in-lane)
    float m = sc[0];
#pragma unroll
    for (int kk = 1; kk < 32; kk++) m = fmaxf(m, sc[kk]);
    float s = 0.0f;
#pragma unroll
    for (int kk = 0; kk < 32; kk++) {
        sc[kk] = __expf(sc[kk] - m);
        s += sc[kk];
    }
    const float inv = 1.0f / s;

    // out = P @ V (v rows warp-uniform broadcasts), normalize at the end
    float o[16];
#pragma unroll
    for (int j = 0; j < 16; j++) o[j] = 0.0f;
#pragma unroll
    for (int kk = 0; kk < 32; kk++) {
        const float4* vp = (const float4*)(s_qkv + kk * QS + 384 + h * 16);
        const float p = sc[kk];
#pragma unroll
        for (int j = 0; j < 4; j++) {
            float4 v = vp[j];
            o[4 * j + 0] += p * v.x;
            o[4 * j + 1] += p * v.y;
            o[4 * j + 2] += p * v.z;
            o[4 * j + 3] += p * v.w;
        }
    }

    float* op = out + (size_t)(n * 32 + qq) * 192 + h * 16;
#pragma unroll
    for (int j = 0; j < 4; j++) {
        float4 w = make_float4(o[4 * j + 0] * inv, o[4 * j + 1] * inv,
                               o[4 * j + 2] * inv, o[4 * j + 3] * inv);
        ((float4*)op)[j] = w;
    }
}

// ----------------------------------------------------------------------------
// launch
// ----------------------------------------------------------------------------
#define GEMM_SMEM ((2 * A_BUF + 2 * B_BUF) * 4)

extern "C" void kernel_launch(void* const* d_in, const int* in_sizes, int n_in,
                              void* d_out, int out_size)
{
    // identify inputs by element count (all distinct) — robust to ordering
    const float* data = nullptr;
    const int* rel_pos = nullptr;
    const float* mask = nullptr;
    const float* qkv_w = nullptr;
    const float* qkv_b = nullptr;
    const float* proj_w = nullptr;
    const float* proj_b = nullptr;
    const float* rpe_table = nullptr;
    for (int i = 0; i < n_in; i++) {
        switch (in_sizes[i]) {
            case 262144 * 192:      data = (const float*)d_in[i]; break;       // 50331648
            case 8192 * 32 * 32 * 3: rel_pos = (const int*)d_in[i]; break;     // 25165824
            case 8192 * 32 * 32:    mask = (const float*)d_in[i]; break;       // 8388608
            case 576 * 192:         qkv_w = (const float*)d_in[i]; break;      // 110592
            case 576:               qkv_b = (const float*)d_in[i]; break;
            case 192 * 192:         proj_w = (const float*)d_in[i]; break;     // 36864
            case 192:               proj_b = (const float*)d_in[i]; break;
            case 153 * 12:          rpe_table = (const float*)d_in[i]; break;  // 1836
            default: break;
        }
    }
    float* out = (float*)d_out;

    float* qkv_s = nullptr;
    float* att_s = nullptr;
    cudaGetSymbolAddress((void**)&qkv_s, g_qkv);
    cudaGetSymbolAddress((void**)&att_s, g_att);

    cudaFuncSetAttribute(gemm_tf32, cudaFuncAttributeMaxDynamicSharedMemorySize, GEMM_SMEM);
    cudaFuncSetAttribute(attn_kernel, cudaFuncAttributeMaxDynamicSharedMemorySize, ATTN_SMEM);

    // 1. QKV projection: [262144,192] @ [576,192]^T + b -> g_qkv  (n-fast grid)
    gemm_tf32<<<dim3(576 / BN, 262144 / BM), 256, GEMM_SMEM>>>(
        data, qkv_w, qkv_b, qkv_s, 262144, 576, 192);

    // 2. per-window attention -> g_att
    attn_kernel<<<N_WIN, 384, ATTN_SMEM>>>(qkv_s, rel_pos, mask, rpe_table, att_s);

    // 3. output projection: [262144,192] @ [192,192]^T + b -> out  (n-fast grid)
    gemm_tf32<<<dim3(192 / BN, 262144 / BM), 256, GEMM_SMEM>>>(
        att_s, proj_w, proj_b, out, 262144, 192, 192);
}